// round 5
// baseline (speedup 1.0000x reference)
#include <cuda_runtime.h>
#include <math.h>

#define HIDDEN 1024
#define NINTER 256
#define WINDOW 64
#define NBLK   32

// persistent scratch (allocation-free rule: __device__ globals; zero-init once)
__device__ double   g_partial[NBLK];
__device__ unsigned g_ticket;          // monotonic across replays: no reset node

// fast fp64 exp, rel err ~1e-13 (range reduction + degree-9 Horner)
__device__ __forceinline__ double fast_exp(double x) {
    const double LOG2E  = 1.4426950408889634074;
    const double LN2_HI = 6.9314718055994528623e-1;
    const double LN2_LO = 2.3190468138462995584e-17;
    double n = rint(x * LOG2E);
    double r = fma(-n, LN2_HI, x);
    r = fma(-n, LN2_LO, r);
    double p = 2.7557319223985890653e-6;
    p = fma(p, r, 2.4801587301587301566e-5);
    p = fma(p, r, 1.9841269841269841253e-4);
    p = fma(p, r, 1.3888888888888889419e-3);
    p = fma(p, r, 8.3333333333333332177e-3);
    p = fma(p, r, 4.1666666666666664354e-2);
    p = fma(p, r, 1.6666666666666665741e-1);
    p = fma(p, r, 5.0e-1);
    p = fma(p, r, 1.0);
    p = fma(p, r, 1.0);
    long long ni = (long long)n;
    double sc = __longlong_as_double((ni + 1023LL) << 52);
    return p * sc;
}

// 1/d via fp32 rcp seed + 2 fp64 Newton steps (no DDIV library chain)
__device__ __forceinline__ double fast_recip(double d) {
    double y = (double)__frcp_rn((float)d);
    y = y * fma(-d, y, 2.0);
    y = y * fma(-d, y, 2.0);
    return y;
}

// ---------------------------------------------------------------------------
// One fused kernel, 32 blocks x 256 threads (all co-resident on 148 SMs).
// A: warp w of block b computes row 8b+w of the MLP, folds tanh*fc2_w -> one
//    fp64 partial per block, published to g_partial[b].
// barrier: 32 atomic tickets to a monotonic counter (replay-safe), tid0 spins.
// B: warp 0 of every block reduces the 32 partials (fixed order), computes
//    p_t / window / e_t with fast_exp + fast_recip.
// C: block b sums rows [ws,we] for columns 32b..32b+31; 17 independent
//    predicated loads per thread (single DRAM-latency batch), smem reduce.
// ---------------------------------------------------------------------------
__global__ void __launch_bounds__(256) fused_attn_kernel(
        const float* __restrict__ hs,
        const float* __restrict__ ht,
        const float* __restrict__ fc1_w,
        const float* __restrict__ fc1_b,
        const float* __restrict__ fc2_w,
        const float* __restrict__ fc2_b,
        float* __restrict__ out, int S) {
    const int tid  = threadIdx.x;
    const int lane = tid & 31;
    const int wid  = tid >> 5;
    const int bid  = blockIdx.x;

    __shared__ double sA[8];
    __shared__ int    sh_ws, sh_we;
    __shared__ float  sh_et;
    __shared__ float  colsum[8][33];   // padded: conflict-free column reads

    // ---------------- Stage A: warp-per-row MLP ----------------
    {
        const int row = (bid << 3) + wid;
        const float4* wp = (const float4*)(fc1_w + (size_t)row * HIDDEN);
        const float4* hp = (const float4*)ht;

        float4 w[8], h[8];
        #pragma unroll
        for (int j = 0; j < 8; j++) w[j] = wp[lane + (j << 5)];
        #pragma unroll
        for (int j = 0; j < 8; j++) h[j] = hp[lane + (j << 5)];
        const float fw = fc2_w[row];
        const float fb = fc1_b[row];

        double a0 = 0.0, a1 = 0.0, a2 = 0.0, a3 = 0.0;
        #pragma unroll
        for (int j = 0; j < 8; j++) {
            a0 += (double)w[j].x * h[j].x;
            a1 += (double)w[j].y * h[j].y;
            a2 += (double)w[j].z * h[j].z;
            a3 += (double)w[j].w * h[j].w;
        }
        double acc = (a0 + a1) + (a2 + a3);
        #pragma unroll
        for (int o = 16; o > 0; o >>= 1)
            acc += __shfl_down_sync(0xffffffffu, acc, o);

        if (lane == 0)
            sA[wid] = (double)tanhf((float)(acc + (double)fb)) * (double)fw;
    }
    __syncthreads();

    // ---------------- publish block partial + ticket barrier ----------------
    if (tid == 0) {
        double p = ((sA[0] + sA[1]) + (sA[2] + sA[3]))
                 + ((sA[4] + sA[5]) + (sA[6] + sA[7]));
        g_partial[bid] = p;
        __threadfence();
        unsigned ticket = atomicAdd(&g_ticket, 1u) + 1u;
        unsigned target = (ticket + (NBLK - 1u)) & ~(NBLK - 1u);
        while (*(volatile unsigned*)&g_ticket < target) { }
    }
    __syncthreads();

    // ---------------- Stage B: head (warp 0, fixed-order reduce) ------------
    if (tid < 32) {
        double v = __ldcg(&g_partial[lane]);
        #pragma unroll
        for (int o = 16; o > 0; o >>= 1)
            v += __shfl_down_sync(0xffffffffu, v, o);
        if (lane == 0) {
            double z  = v + (double)fc2_b[0];
            double e  = fast_exp(-z);
            double pt = (double)S * fast_recip(1.0 + e);
            double wsd = ceil(pt - (double)WINDOW);
            if (wsd < 0.0) wsd = 0.0;
            double wed = floor(pt + (double)WINDOW);
            if (wed > (double)(S - 1)) wed = (double)(S - 1);
            sh_ws = (int)wsd;
            sh_we = (int)wed;
            sh_et = expf((float)(((double)S - pt) * (1.0 / 2048.0)));
        }
    }
    __syncthreads();

    // ---------------- Stage C: windowed row-sum, 32 cols per block ----------
    {
        const int ws = sh_ws;
        const int we = sh_we;
        const int col = (bid << 5) + lane;
        const int r0  = ws + wid;               // wid = row group 0..7
        const float* base = hs + col;

        // window <= 129 rows; groups stride 8 -> <=17 slots, all independent
        float t0 = 0.f, t1 = 0.f, t2 = 0.f, t3 = 0.f;
        #pragma unroll
        for (int i = 0; i < 17; i += 4) {
            int r = r0 + (i << 3);
            if (r <= we)                  t0 += base[(size_t)r * HIDDEN];
            if (i + 1 < 17 && r + 8  <= we) t1 += base[(size_t)(r + 8)  * HIDDEN];
            if (i + 2 < 17 && r + 16 <= we) t2 += base[(size_t)(r + 16) * HIDDEN];
            if (i + 3 < 17 && r + 24 <= we) t3 += base[(size_t)(r + 24) * HIDDEN];
        }
        colsum[wid][lane] = (t0 + t1) + (t2 + t3);
    }
    __syncthreads();

    if (tid < 32) {
        float s = 0.f;
        #pragma unroll
        for (int g = 0; g < 8; g++) s += colsum[g][tid];
        out[(bid << 5) + tid] = sh_et * s;
    }
}

extern "C" void kernel_launch(void* const* d_in, const int* in_sizes, int n_in,
                              void* d_out, int out_size) {
    const float* hs    = (const float*)d_in[0];
    const float* ht    = (const float*)d_in[1];
    const float* fc1_w = (const float*)d_in[2];
    const float* fc1_b = (const float*)d_in[3];
    const float* fc2_w = (const float*)d_in[4];
    const float* fc2_b = (const float*)d_in[5];

    const int S = in_sizes[0] / HIDDEN;   // host-side constant, capture-safe

    fused_attn_kernel<<<NBLK, 256>>>(hs, ht, fc1_w, fc1_b, fc2_w, fc2_b,
                                     (float*)d_out, S);
}

// round 7
// speedup vs baseline: 1.3005x; 1.3005x over previous
#include <cuda_runtime.h>
#include <math.h>

#define HIDDEN 1024
#define NINTER 256
#define WINDOW 64
#define PAD    24      // speculative pad, rows (estimate error bound ~0.05 rows)

// per-row tanh(z_i) * fc2_w[i], fp64 (allocation-free rule: __device__ global)
__device__ double g_p[NINTER];

// fp64 exp, rel err ~1e-13 (range reduction + degree-9, Estrin form)
__device__ __forceinline__ double fast_exp(double x) {
    const double LOG2E  = 1.4426950408889634074;
    const double LN2_HI = 6.9314718055994528623e-1;
    const double LN2_LO = 2.3190468138462995584e-17;
    double n = rint(x * LOG2E);
    double r = fma(-n, LN2_HI, x);
    r = fma(-n, LN2_LO, r);
    double p01 = 1.0 + r;
    double p23 = fma(r, 1.6666666666666665741e-1, 5.0e-1);
    double p45 = fma(r, 8.3333333333333332177e-3, 4.1666666666666664354e-2);
    double p67 = fma(r, 1.9841269841269841253e-4, 1.3888888888888889419e-3);
    double p89 = fma(r, 2.7557319223985890653e-6, 2.4801587301587301566e-5);
    double r2 = r * r;
    double q0 = fma(r2, p23, p01);
    double q1 = fma(r2, p67, p45);
    double r4 = r2 * r2;
    double s0 = fma(r4, q1, q0);
    double r8 = r4 * r4;
    double res = fma(r8, p89, s0);
    long long ni = (long long)n;
    double sc = __longlong_as_double((ni + 1023LL) << 52);  // exact 2^n
    return res * sc;
}

// 1/d via fp32 rcp seed + 1 fp64 Newton step (rel err ~2^-44)
__device__ __forceinline__ double fast_recip(double d) {
    double y = (double)__frcp_rn((float)d);
    return y * fma(-d, y, 2.0);
}

// ---------------------------------------------------------------------------
// Kernel 1: g_p[row] = tanhf(dot_fp64(fc1_w[row,:], h_t) + fc1_b[row]) * fc2_w[row]
// Block-per-row (structure identical to the R4 passing kernel).
// ---------------------------------------------------------------------------
__global__ void __launch_bounds__(256) mlp1_kernel(
        const float* __restrict__ ht,
        const float* __restrict__ fc1_w,
        const float* __restrict__ fc1_b,
        const float* __restrict__ fc2_w) {
    const int tid  = threadIdx.x;
    const int lane = tid & 31;
    const int wid  = tid >> 5;

    float4 w = ((const float4*)(fc1_w + (size_t)blockIdx.x * HIDDEN))[tid];
    float4 h = ((const float4*)ht)[tid];
    double acc = (double)w.x * h.x + (double)w.y * h.y
               + (double)w.z * h.z + (double)w.w * h.w;
    #pragma unroll
    for (int o = 16; o > 0; o >>= 1)
        acc += __shfl_down_sync(0xffffffffu, acc, o);

    __shared__ double s[8];
    if (lane == 0) s[wid] = acc;
    __syncthreads();
    if (tid == 0) {
        double z = ((s[0] + s[1]) + (s[2] + s[3]))
                 + ((s[4] + s[5]) + (s[6] + s[7]))
                 + (double)fc1_b[blockIdx.x];
        g_p[blockIdx.x] = (double)tanhf((float)z) * (double)fc2_w[blockIdx.x];
    }
}

// ---------------------------------------------------------------------------
// Kernel 2: speculative windowed row-sum.
//  reduce terms -> tid0 publishes a FAST estimate of the window base
//  (fp64 sum INCLUDING fc2_b, fp32 exp/rcp; error << 1 row) -> all threads
//  issue padded loads (192-row span, +-24 pad) -> tid0 computes the EXACT
//  fp64 head under the load latency -> mask rows by exact [ws,we] -> reduce.
// ---------------------------------------------------------------------------
__global__ void __launch_bounds__(256) windowsum_kernel(
        const float* __restrict__ hs,
        const float* __restrict__ fc2_b,
        float* __restrict__ out, int S) {
    const int tid  = threadIdx.x;
    const int lane = tid & 31;
    const int wid  = tid >> 5;

    __shared__ double sred[8];
    __shared__ int    sh_est_lo;
    __shared__ int    sh_ws, sh_we;
    __shared__ float  sh_et;
    __shared__ float  colsum[256];

    // per-thread term (written by K1; kernel boundary = full barrier)
    double term = __ldcg(&g_p[tid]);
    #pragma unroll
    for (int o = 16; o > 0; o >>= 1)
        term += __shfl_down_sync(0xffffffffu, term, o);
    if (lane == 0) sred[wid] = term;
    __syncthreads();

    // fast estimate (tid0): fp64 z INCLUDING fc2_b, then fp32 exp/rcp
    if (tid == 0) {
        double zd = ((sred[0] + sred[1]) + (sred[2] + sred[3]))
                  + ((sred[4] + sred[5]) + (sred[6] + sred[7]))
                  + (double)fc2_b[0];
        float zf  = (float)zd;
        float ptf = (float)S * __frcp_rn(1.0f + __expf(-zf));
        int lo = (int)ptf - ((WINDOW - 1) + PAD);
        if (lo < 0) lo = 0;
        sh_est_lo = lo;
    }
    __syncthreads();

    // padded window loads (3 independent predicated loads per thread)
    const int est_lo = sh_est_lo;
    const int col    = (blockIdx.x << 2) + (tid & 3);
    const int rowoff = tid >> 2;                       // 0..63
    const int r0 = est_lo + rowoff;
    const int r1 = r0 + 64;
    const int r2 = r0 + 128;
    const float* base = hs + col;

    float v0 = 0.f, v1 = 0.f, v2 = 0.f;
    if (r0 < S) v0 = base[(size_t)r0 * HIDDEN];
    if (r1 < S) v1 = base[(size_t)r1 * HIDDEN];
    if (r2 < S) v2 = base[(size_t)r2 * HIDDEN];

    // exact fp64 head (tid0) overlapping the loads above
    if (tid == 0) {
        double z = ((sred[0] + sred[1]) + (sred[2] + sred[3]))
                 + ((sred[4] + sred[5]) + (sred[6] + sred[7]))
                 + (double)fc2_b[0];
        double e  = fast_exp(-z);
        double pt = (double)S * fast_recip(1.0 + e);
        // pt in (0,S), non-integer: ceil(pt-64)=floor(pt)-63, floor(pt+64)=floor(pt)+64
        int k = (int)pt;
        int ws = k - (WINDOW - 1);  if (ws < 0)     ws = 0;
        int we = k + WINDOW;        if (we > S - 1) we = S - 1;
        sh_ws = ws;
        sh_we = we;
        sh_et = __expf((float)(((double)S - pt) * (1.0 / 2048.0)));
    }
    __syncthreads();

    // mask by the exact window (pad guarantees coverage) and reduce
    const int ws = sh_ws;
    const int we = sh_we;
    float acc = 0.f;
    if (r0 >= ws && r0 <= we) acc += v0;
    if (r1 >= ws && r1 <= we) acc += v1;
    if (r2 >= ws && r2 <= we) acc += v2;
    colsum[tid] = acc;
    __syncthreads();

    if (tid < 128) colsum[tid] += colsum[tid + 128];
    __syncthreads();
    if (tid < 64)  colsum[tid] += colsum[tid + 64];
    __syncthreads();
    if (tid < 32) {
        colsum[tid] += colsum[tid + 32];
        __syncwarp(0xffffffffu);
        if (tid < 16) colsum[tid] += colsum[tid + 16];
        __syncwarp(0xffffffffu);
        if (tid < 8)  colsum[tid] += colsum[tid + 8];
        __syncwarp(0xffffffffu);
        if (tid < 4)
            out[col] = sh_et * (colsum[tid] + colsum[tid + 4]);
    }
}

extern "C" void kernel_launch(void* const* d_in, const int* in_sizes, int n_in,
                              void* d_out, int out_size) {
    const float* hs    = (const float*)d_in[0];
    const float* ht    = (const float*)d_in[1];
    const float* fc1_w = (const float*)d_in[2];
    const float* fc1_b = (const float*)d_in[3];
    const float* fc2_w = (const float*)d_in[4];
    const float* fc2_b = (const float*)d_in[5];

    const int S = in_sizes[0] / HIDDEN;   // host-side constant, capture-safe

    mlp1_kernel<<<NINTER, 256>>>(ht, fc1_w, fc1_b, fc2_w);
    windowsum_kernel<<<NINTER, 256>>>(hs, fc2_b, (float*)d_out, S);
}

// round 8
// speedup vs baseline: 1.3233x; 1.0175x over previous
#include <cuda_runtime.h>
#include <math.h>

#define HIDDEN 1024
#define NINTER 256
#define WINDOW 64
#define PAD    24      // speculative pad, rows (estimate error bound << 1 row)

// per-row tanh(z_i) * fc2_w[i], fp64 (allocation-free rule: __device__ global)
__device__ double g_p[NINTER];

// fp64 exp, rel err ~1e-13 (range reduction + degree-9, Estrin form)
__device__ __forceinline__ double fast_exp(double x) {
    const double LOG2E  = 1.4426950408889634074;
    const double LN2_HI = 6.9314718055994528623e-1;
    const double LN2_LO = 2.3190468138462995584e-17;
    double n = rint(x * LOG2E);
    double r = fma(-n, LN2_HI, x);
    r = fma(-n, LN2_LO, r);
    double p01 = 1.0 + r;
    double p23 = fma(r, 1.6666666666666665741e-1, 5.0e-1);
    double p45 = fma(r, 8.3333333333333332177e-3, 4.1666666666666664354e-2);
    double p67 = fma(r, 1.9841269841269841253e-4, 1.3888888888888889419e-3);
    double p89 = fma(r, 2.7557319223985890653e-6, 2.4801587301587301566e-5);
    double r2 = r * r;
    double q0 = fma(r2, p23, p01);
    double q1 = fma(r2, p67, p45);
    double r4 = r2 * r2;
    double s0 = fma(r4, q1, q0);
    double r8 = r4 * r4;
    double res = fma(r8, p89, s0);
    long long ni = (long long)n;
    double sc = __longlong_as_double((ni + 1023LL) << 52);  // exact 2^n
    return res * sc;
}

// 1/d via fp32 rcp seed + 1 fp64 Newton step (rel err ~2^-44)
__device__ __forceinline__ double fast_recip(double d) {
    double y = (double)__frcp_rn((float)d);
    return y * fma(-d, y, 2.0);
}

// ---------------------------------------------------------------------------
// Kernel 1: g_p[row] = tanhf(dot_fp64(fc1_w[row,:], h_t) + fc1_b[row]) * fc2_w[row]
// Block-per-row. Signals PDL launch_dependents IMMEDIATELY so K2's CTAs roll
// out and run their prologue concurrently with this kernel's body.
// ---------------------------------------------------------------------------
__global__ void __launch_bounds__(256) mlp1_kernel(
        const float* __restrict__ ht,
        const float* __restrict__ fc1_w,
        const float* __restrict__ fc1_b,
        const float* __restrict__ fc2_w) {
    asm volatile("griddepcontrol.launch_dependents;" ::: "memory");

    const int tid  = threadIdx.x;
    const int lane = tid & 31;
    const int wid  = tid >> 5;

    float4 w = ((const float4*)(fc1_w + (size_t)blockIdx.x * HIDDEN))[tid];
    float4 h = ((const float4*)ht)[tid];
    // depth-3 parallel dot (2 independent DFMA chains + join)
    double e0 = fma((double)w.y, (double)h.y, (double)w.x * h.x);
    double e1 = fma((double)w.w, (double)h.w, (double)w.z * h.z);
    double acc = e0 + e1;
    #pragma unroll
    for (int o = 16; o > 0; o >>= 1)
        acc += __shfl_down_sync(0xffffffffu, acc, o);

    __shared__ double s[8];
    if (lane == 0) s[wid] = acc;
    __syncthreads();
    if (tid == 0) {
        double z = ((s[0] + s[1]) + (s[2] + s[3]))
                 + ((s[4] + s[5]) + (s[6] + s[7]))
                 + (double)fc1_b[blockIdx.x];
        g_p[blockIdx.x] = (double)tanhf((float)z) * (double)fc2_w[blockIdx.x];
    }
}

// ---------------------------------------------------------------------------
// Kernel 2 (PDL dependent): prologue (index math) runs under K1; then
// griddepcontrol.wait; then the R7 speculative windowed row-sum.
// ---------------------------------------------------------------------------
__global__ void __launch_bounds__(256) windowsum_kernel(
        const float* __restrict__ hs,
        const float* __restrict__ fc2_b,
        float* __restrict__ out, int S) {
    const int tid  = threadIdx.x;
    const int lane = tid & 31;
    const int wid  = tid >> 5;

    __shared__ double sred[8];
    __shared__ int    sh_est_lo;
    __shared__ int    sh_ws, sh_we;
    __shared__ float  sh_et;
    __shared__ float  colsum[8][36];   // [warp][col-slot], padded

    // prologue independent of K1 — overlaps K1's execution under PDL
    const int col    = (blockIdx.x << 2) + (tid & 3);
    const int rowoff = tid >> 2;                       // 0..63
    const float* base = hs + col;

    // hardware-wait for K1 completion + memory visibility
    asm volatile("griddepcontrol.wait;" ::: "memory");

    double term = __ldcg(&g_p[tid]);
    #pragma unroll
    for (int o = 16; o > 0; o >>= 1)
        term += __shfl_down_sync(0xffffffffu, term, o);
    if (lane == 0) sred[wid] = term;
    __syncthreads();

    // fast estimate (tid0): fp64 z INCLUDING fc2_b, fp32 exp/rcp (err << 1 row)
    if (tid == 0) {
        double zd = ((sred[0] + sred[1]) + (sred[2] + sred[3]))
                  + ((sred[4] + sred[5]) + (sred[6] + sred[7]))
                  + (double)fc2_b[0];
        float zf  = (float)zd;
        float ptf = (float)S * __frcp_rn(1.0f + __expf(-zf));
        int lo = (int)ptf - ((WINDOW - 1) + PAD);
        if (lo < 0) lo = 0;
        sh_est_lo = lo;
    }
    __syncthreads();

    // padded window loads (3 independent predicated loads per thread)
    const int est_lo = sh_est_lo;
    const int r0 = est_lo + rowoff;
    const int r1 = r0 + 64;
    const int r2 = r0 + 128;

    float v0 = 0.f, v1 = 0.f, v2 = 0.f;
    if (r0 < S) v0 = base[(size_t)r0 * HIDDEN];
    if (r1 < S) v1 = base[(size_t)r1 * HIDDEN];
    if (r2 < S) v2 = base[(size_t)r2 * HIDDEN];

    // exact fp64 head (tid0) overlapping the loads above
    if (tid == 0) {
        double z = ((sred[0] + sred[1]) + (sred[2] + sred[3]))
                 + ((sred[4] + sred[5]) + (sred[6] + sred[7]))
                 + (double)fc2_b[0];
        double e  = fast_exp(-z);
        double pt = (double)S * fast_recip(1.0 + e);
        // pt in (0,S), non-integer: ceil(pt-64)=floor(pt)-63, floor(pt+64)=floor(pt)+64
        int k = (int)pt;
        int ws = k - (WINDOW - 1);  if (ws < 0)     ws = 0;
        int we = k + WINDOW;        if (we > S - 1) we = S - 1;
        sh_ws = ws;
        sh_we = we;
        sh_et = __expf((float)(((double)S - pt) * (1.0 / 2048.0)));
    }
    __syncthreads();

    // mask by the exact window (pad guarantees coverage)
    const int ws = sh_ws;
    const int we = sh_we;
    float acc = 0.f;
    if (r0 >= ws && r0 <= we) acc += v0;
    if (r1 >= ws && r1 <= we) acc += v1;
    if (r2 >= ws && r2 <= we) acc += v2;

    // warp-level reduce: lanes within a warp hold 8 rowgroups of the same
    // 4 columns interleaved -> xor-shuffle folds rowgroups, keeps columns.
    #pragma unroll
    for (int o = 16; o >= 4; o >>= 1)
        acc += __shfl_xor_sync(0xffffffffu, acc, o);
    if (lane < 4) colsum[wid][lane] = acc;   // 8 warps x 4 cols
    __syncthreads();

    if (tid < 4) {
        float s = ((colsum[0][tid] + colsum[1][tid])
                 + (colsum[2][tid] + colsum[3][tid]))
                + ((colsum[4][tid] + colsum[5][tid])
                 + (colsum[6][tid] + colsum[7][tid]));
        out[col] = sh_et * s;
    }
}

extern "C" void kernel_launch(void* const* d_in, const int* in_sizes, int n_in,
                              void* d_out, int out_size) {
    const float* hs    = (const float*)d_in[0];
    const float* ht    = (const float*)d_in[1];
    const float* fc1_w = (const float*)d_in[2];
    const float* fc1_b = (const float*)d_in[3];
    const float* fc2_w = (const float*)d_in[4];
    const float* fc2_b = (const float*)d_in[5];

    const int S = in_sizes[0] / HIDDEN;   // host-side constant, capture-safe

    mlp1_kernel<<<NINTER, 256>>>(ht, fc1_w, fc1_b, fc2_w);

    // K2 as a PDL dependent launch: rolls out while K1 runs
    cudaLaunchConfig_t cfg = {};
    cfg.gridDim  = dim3(NINTER, 1, 1);
    cfg.blockDim = dim3(256, 1, 1);
    cfg.dynamicSmemBytes = 0;
    cfg.stream = 0;
    cudaLaunchAttribute attr[1];
    attr[0].id = cudaLaunchAttributeProgrammaticStreamSerialization;
    attr[0].val.programmaticStreamSerializationAllowed = 1;
    cfg.attrs = attr;
    cfg.numAttrs = 1;
    float* outp = (float*)d_out;
    cudaLaunchKernelEx(&cfg, windowsum_kernel, hs, fc2_b, outp, S);
}